// round 15
// baseline (speedup 1.0000x reference)
#include <cuda_runtime.h>
#include <cuda_bf16.h>
#include <math.h>
#include <stdint.h>

#define N_NODES 100000
#define N_EDGES 1600000
#define IN_DIM  128
#define HID_DIM 256
#define OUT_DIM 128

// ---------------- scratch (device globals; no allocation allowed) ----------
__device__ int   g_is64;
__device__ int   g_deg[N_NODES];
__device__ int   g_cur[N_NODES];
__device__ int   g_rowptr[N_NODES + 1];
__device__ float g_dinv[N_NODES];
__device__ __align__(16) int2 g_edge[N_EDGES];         // (src, weight-as-int)
// layer-1 A (aggregated x) as bf16 hi/lo images [N,128]
__device__ __align__(16) unsigned short g_a1hi[(size_t)N_NODES * IN_DIM];
__device__ __align__(16) unsigned short g_a1lo[(size_t)N_NODES * IN_DIM];
// layer-2 A (relu(h1)) as bf16 hi/lo images [N,256]
__device__ __align__(16) unsigned short g_h1hi[(size_t)N_NODES * HID_DIM];
__device__ __align__(16) unsigned short g_h1lo[(size_t)N_NODES * HID_DIM];
__device__ __align__(16) float g_z[(size_t)N_NODES * OUT_DIM];     // h1@W2 [N,128]
// weight images W^T: [N][K] k-major bf16, hi/lo split
__device__ __align__(16) unsigned short g_w1hi[256 * 128];
__device__ __align__(16) unsigned short g_w1lo[256 * 128];
__device__ __align__(16) unsigned short g_w2hi[128 * 256];
__device__ __align__(16) unsigned short g_w2lo[128 * 256];

// ---------------- warp-level bf16 MMA (base-target PTX, runs on HMMA) ------
#define MMA_BF16(c, a, b)                                                        \
    asm volatile("mma.sync.aligned.m16n8k16.row.col.f32.bf16.bf16.f32 "          \
        "{%0,%1,%2,%3}, {%4,%5,%6,%7}, {%8,%9}, {%0,%1,%2,%3};"                  \
        : "+f"((c)[0]), "+f"((c)[1]), "+f"((c)[2]), "+f"((c)[3])                 \
        : "r"((a)[0]), "r"((a)[1]), "r"((a)[2]), "r"((a)[3]),                    \
          "r"((b)[0]), "r"((b)[1]))

#define CP_ASYNC16(dst_u32, src_ptr)                                             \
    asm volatile("cp.async.ca.shared.global [%0], [%1], 16;"                     \
                 :: "r"(dst_u32), "l"(src_ptr) : "memory")
#define CP_COMMIT() asm volatile("cp.async.commit_group;" ::: "memory")
#define CP_WAIT0()  asm volatile("cp.async.wait_group 0;" ::: "memory")

__device__ __forceinline__ uint32_t smem_u32(const void* p) {
    uint32_t a;
    asm("{ .reg .u64 t; cvta.to.shared.u64 t, %1; cvt.u32.u64 %0, t; }" : "=r"(a) : "l"(p));
    return a;
}

__device__ __forceinline__ void split2(float x, float y, uint32_t& hp, uint32_t& lp) {
    __nv_bfloat16 h0 = __float2bfloat16(x);
    __nv_bfloat16 h1 = __float2bfloat16(y);
    __nv_bfloat16 l0 = __float2bfloat16(x - __bfloat162float(h0));
    __nv_bfloat16 l1 = __float2bfloat16(y - __bfloat162float(h1));
    hp = ((uint32_t)*(unsigned short*)&h1 << 16) | *(unsigned short*)&h0;
    lp = ((uint32_t)*(unsigned short*)&l1 << 16) | *(unsigned short*)&l0;
}

// ---------------- edge_index accessors --------------------------------------
__device__ __forceinline__ int edge_src(const int* e32, int e) {
    int v = g_is64 ? e32[2 * e] : e32[e];
    return min(max(v, 0), N_NODES - 1);
}
__device__ __forceinline__ int edge_dst(const int* e32, int e) {
    int v = g_is64 ? e32[2 * (N_EDGES + e)] : e32[N_EDGES + e];
    return min(max(v, 0), N_NODES - 1);
}

// ---------------- init: zero deg/cursor + int64 dtype probe -----------------
__global__ void k_init(const int* e32) {
    int i = blockIdx.x * blockDim.x + threadIdx.x;
    if (i < N_NODES) { g_deg[i] = 0; g_cur[i] = 0; }
    if (i == 0) {
        int zeros = 0;
        for (int k = 0; k < 1024; k++) zeros += (e32[2 * k + 1] == 0) ? 1 : 0;
        g_is64 = (zeros > 512) ? 1 : 0;
    }
}

__global__ void k_count(const int* e32) {
    int e = blockIdx.x * blockDim.x + threadIdx.x;
    if (e < N_EDGES) atomicAdd(&g_deg[edge_dst(e32, e)], 1);
}

__global__ void k_scan() {
    __shared__ int sums[1024];
    const int n = N_NODES;
    int t = threadIdx.x;
    const int chunk = (n + 1023) / 1024;
    int beg = t * chunk;
    int end = min(beg + chunk, n);
    if (beg > end) beg = end;
    int s = 0;
    for (int i = beg; i < end; i++) {
        int d = g_deg[i];
        s += d;
        g_dinv[i] = rsqrtf((float)(d + 1));
    }
    sums[t] = s;
    __syncthreads();
    for (int off = 1; off < 1024; off <<= 1) {
        int v = (t >= off) ? sums[t - off] : 0;
        __syncthreads();
        sums[t] += v;
        __syncthreads();
    }
    int run = (t == 0) ? 0 : sums[t - 1];
    for (int i = beg; i < end; i++) { g_rowptr[i] = run; run += g_deg[i]; }
    if (t == 1023) g_rowptr[n] = sums[1023];
}

// scatter edges (dst-sorted) with precomputed weight dinv[s]*dinv[d]
__global__ void k_scatter(const int* e32) {
    int e = blockIdx.x * blockDim.x + threadIdx.x;
    if (e < N_EDGES) {
        int s = edge_src(e32, e);
        int d = edge_dst(e32, e);
        int p = atomicAdd(&g_cur[d], 1);
        float w = g_dinv[s] * g_dinv[d];
        g_edge[g_rowptr[d] + p] = make_int2(s, __float_as_int(w));
    }
}

// ---------------- weight prep (both layers, one launch) ---------------------
__global__ void k_prep_w(const float* W1, const float* W2) {
    int idx = blockIdx.x * blockDim.x + threadIdx.x;
    if (idx < 128 * 256) {                 // W1[128k,256n] -> g_w1*[n][k]
        int n = idx & 255, k = idx >> 8;
        float x = W1[k * 256 + n];
        __nv_bfloat16 h = __float2bfloat16(x);
        __nv_bfloat16 l = __float2bfloat16(x - __bfloat162float(h));
        g_w1hi[n * 128 + k] = *(unsigned short*)&h;
        g_w1lo[n * 128 + k] = *(unsigned short*)&l;
    } else if (idx < 2 * 128 * 256) {      // W2[256k,128n] -> g_w2*[n][k]
        int r = idx - 128 * 256;
        int n = r & 127, k = r >> 7;
        float x = W2[k * 128 + n];
        __nv_bfloat16 h = __float2bfloat16(x);
        __nv_bfloat16 l = __float2bfloat16(x - __bfloat162float(h));
        g_w2hi[n * 256 + k] = *(unsigned short*)&h;
        g_w2lo[n * 256 + k] = *(unsigned short*)&l;
    }
}

// ---------------- aggregation core (8-unrolled, packed edge reads) ----------
__device__ __forceinline__ float4 agg_core(const float4* xi, int i, int lane) {
    float di = g_dinv[i];
    float4 xv = xi[(size_t)i * 32 + lane];
    float w = di * di;
    float4 acc;
    acc.x = w * xv.x; acc.y = w * xv.y; acc.z = w * xv.z; acc.w = w * xv.w;

    int j = g_rowptr[i];
    int end = g_rowptr[i + 1];
    for (; j + 7 < end; j += 8) {
        int2 e0 = g_edge[j],     e1 = g_edge[j + 1];
        int2 e2 = g_edge[j + 2], e3 = g_edge[j + 3];
        int2 e4 = g_edge[j + 4], e5 = g_edge[j + 5];
        int2 e6 = g_edge[j + 6], e7 = g_edge[j + 7];
        float4 v0 = xi[(size_t)e0.x * 32 + lane];
        float4 v1 = xi[(size_t)e1.x * 32 + lane];
        float4 v2 = xi[(size_t)e2.x * 32 + lane];
        float4 v3 = xi[(size_t)e3.x * 32 + lane];
        float4 v4 = xi[(size_t)e4.x * 32 + lane];
        float4 v5 = xi[(size_t)e5.x * 32 + lane];
        float4 v6 = xi[(size_t)e6.x * 32 + lane];
        float4 v7 = xi[(size_t)e7.x * 32 + lane];
        float w0 = __int_as_float(e0.y), w1 = __int_as_float(e1.y);
        float w2 = __int_as_float(e2.y), w3 = __int_as_float(e3.y);
        float w4 = __int_as_float(e4.y), w5 = __int_as_float(e5.y);
        float w6 = __int_as_float(e6.y), w7 = __int_as_float(e7.y);
        acc.x += ((w0 * v0.x + w1 * v1.x) + (w2 * v2.x + w3 * v3.x))
               + ((w4 * v4.x + w5 * v5.x) + (w6 * v6.x + w7 * v7.x));
        acc.y += ((w0 * v0.y + w1 * v1.y) + (w2 * v2.y + w3 * v3.y))
               + ((w4 * v4.y + w5 * v5.y) + (w6 * v6.y + w7 * v7.y));
        acc.z += ((w0 * v0.z + w1 * v1.z) + (w2 * v2.z + w3 * v3.z))
               + ((w4 * v4.z + w5 * v5.z) + (w6 * v6.z + w7 * v7.z));
        acc.w += ((w0 * v0.w + w1 * v1.w) + (w2 * v2.w + w3 * v3.w))
               + ((w4 * v4.w + w5 * v5.w) + (w6 * v6.w + w7 * v7.w));
    }
    for (; j < end; j++) {
        int2 e0 = g_edge[j];
        float w0 = __int_as_float(e0.y);
        float4 v0 = xi[(size_t)e0.x * 32 + lane];
        acc.x += w0 * v0.x; acc.y += w0 * v0.y; acc.z += w0 * v0.z; acc.w += w0 * v0.w;
    }
    return acc;
}

// pass 1: gather x fp32, write bf16 hi/lo images for GEMM1
__global__ void k_agg_x(const float* xin) {
    int warp = threadIdx.x >> 5;
    int lane = threadIdx.x & 31;
    int i = blockIdx.x * 8 + warp;
    if (i >= N_NODES) return;
    float4 acc = agg_core((const float4*)xin, i, lane);
    uint2 hp, lp;
    split2(acc.x, acc.y, hp.x, lp.x);
    split2(acc.z, acc.w, hp.y, lp.y);
    ((uint2*)g_a1hi)[(size_t)i * 32 + lane] = hp;
    ((uint2*)g_a1lo)[(size_t)i * 32 + lane] = lp;
}

// pass 2: gather g_z fp32, add bias, write final output fp32
__global__ void k_agg_out(const float* b2, float* out) {
    int warp = threadIdx.x >> 5;
    int lane = threadIdx.x & 31;
    int i = blockIdx.x * 8 + warp;
    if (i >= N_NODES) return;
    float4 acc = agg_core((const float4*)g_z, i, lane);
    acc.x += b2[lane * 4 + 0];
    acc.y += b2[lane * 4 + 1];
    acc.z += b2[lane * 4 + 2];
    acc.w += b2[lane * 4 + 3];
    ((float4*)out)[(size_t)i * 32 + lane] = acc;
}

// ---------------- bf16 split GEMM via mma.sync + cp.async tile loads --------
#define SMS 72
#define SM_BYTES (4 * 128 * SMS * 2)

template <int LAYER>
__global__ __launch_bounds__(512, 2) void k_mma(const float* bias)
{
    constexpr int KTOT = (LAYER == 1) ? 128 : 256;
    constexpr int KH   = KTOT / 64;
    const unsigned short* AHIg = (LAYER == 1) ? g_a1hi : g_h1hi;
    const unsigned short* ALOg = (LAYER == 1) ? g_a1lo : g_h1lo;
    const unsigned short* WHI  = (LAYER == 1) ? g_w1hi : g_w2hi;
    const unsigned short* WLO  = (LAYER == 1) ? g_w1lo : g_w2lo;

    extern __shared__ __align__(16) unsigned short sm[];
    unsigned short* AHI = sm;
    unsigned short* ALO = sm + 128 * SMS;
    unsigned short* BHI = sm + 2 * 128 * SMS;
    unsigned short* BLO = sm + 3 * 128 * SMS;

    int tid  = threadIdx.x;
    int lane = tid & 31;
    int wid  = tid >> 5;
    int row0 = blockIdx.x * 128;
    int nc0  = blockIdx.y * 128;

    int lr = tid >> 2;
    int cb = (tid & 3) * 16;
    int gr = min(row0 + lr, N_NODES - 1);
    uint32_t sa_hi = smem_u32(&AHI[lr * SMS + cb]);
    uint32_t sa_lo = smem_u32(&ALO[lr * SMS + cb]);
    uint32_t sb_hi = smem_u32(&BHI[lr * SMS + cb]);
    uint32_t sb_lo = smem_u32(&BLO[lr * SMS + cb]);

    float c[2][4][4];
#pragma unroll
    for (int i = 0; i < 2; i++)
#pragma unroll
        for (int j = 0; j < 4; j++)
#pragma unroll
            for (int q = 0; q < 4; q++) c[i][j][q] = 0.0f;

    for (int h = 0; h < KH; h++) {
        const unsigned short* pah = AHIg + (size_t)gr * KTOT + h * 64 + cb;
        const unsigned short* pal = ALOg + (size_t)gr * KTOT + h * 64 + cb;
        const unsigned short* pbh = WHI + (size_t)(nc0 + lr) * KTOT + h * 64 + cb;
        const unsigned short* pbl = WLO + (size_t)(nc0 + lr) * KTOT + h * 64 + cb;
        CP_ASYNC16(sa_hi,      pah);
        CP_ASYNC16(sa_hi + 16, pah + 8);
        CP_ASYNC16(sa_lo,      pal);
        CP_ASYNC16(sa_lo + 16, pal + 8);
        CP_ASYNC16(sb_hi,      pbh);
        CP_ASYNC16(sb_hi + 16, pbh + 8);
        CP_ASYNC16(sb_lo,      pbl);
        CP_ASYNC16(sb_lo + 16, pbl + 8);
        CP_COMMIT();
        CP_WAIT0();
        __syncthreads();

        int mr = (wid & 3) * 32 + (lane >> 2);
        int nr = (wid >> 2) * 32 + (lane >> 2);
#pragma unroll
        for (int k0 = 0; k0 < 64; k0 += 16) {
            int kc = k0 + (lane & 3) * 2;
            uint32_t ah[2][4], al[2][4], bh[4][2], bl[4][2];
#pragma unroll
            for (int i = 0; i < 2; i++) {
                int base = (mr + 16 * i) * SMS + kc;
                ah[i][0] = *(const uint32_t*)&AHI[base];
                ah[i][1] = *(const uint32_t*)&AHI[base + 8 * SMS];
                ah[i][2] = *(const uint32_t*)&AHI[base + 8];
                ah[i][3] = *(const uint32_t*)&AHI[base + 8 * SMS + 8];
                al[i][0] = *(const uint32_t*)&ALO[base];
                al[i][1] = *(const uint32_t*)&ALO[base + 8 * SMS];
                al[i][2] = *(const uint32_t*)&ALO[base + 8];
                al[i][3] = *(const uint32_t*)&ALO[base + 8 * SMS + 8];
            }
#pragma unroll
            for (int j = 0; j < 4; j++) {
                int base = (nr + 8 * j) * SMS + kc;
                bh[j][0] = *(const uint32_t*)&BHI[base];
                bh[j][1] = *(const uint32_t*)&BHI[base + 8];
                bl[j][0] = *(const uint32_t*)&BLO[base];
                bl[j][1] = *(const uint32_t*)&BLO[base + 8];
            }
#pragma unroll
            for (int i = 0; i < 2; i++)
#pragma unroll
                for (int j = 0; j < 4; j++) {
                    MMA_BF16(c[i][j], ah[i], bh[j]);
                    MMA_BF16(c[i][j], ah[i], bl[j]);
                    MMA_BF16(c[i][j], al[i], bh[j]);
                }
        }
        __syncthreads();
    }

    // ---- epilogue
    int m0 = (wid & 3) * 32;
    int n0 = (wid >> 2) * 32;
#pragma unroll
    for (int i = 0; i < 2; i++) {
#pragma unroll
        for (int j = 0; j < 4; j++) {
            int row = row0 + m0 + 16 * i + (lane >> 2);
            int col = nc0 + n0 + 8 * j + (lane & 3) * 2;
            if (LAYER == 1) {
                float b0 = bias[col], b1 = bias[col + 1];
                float v0x = fmaxf(c[i][j][0] + b0, 0.0f);
                float v0y = fmaxf(c[i][j][1] + b1, 0.0f);
                float v1x = fmaxf(c[i][j][2] + b0, 0.0f);
                float v1y = fmaxf(c[i][j][3] + b1, 0.0f);
                uint32_t hp0, lp0, hp1, lp1;
                split2(v0x, v0y, hp0, lp0);
                split2(v1x, v1y, hp1, lp1);
                if (row < N_NODES) {
                    *(uint32_t*)&g_h1hi[(size_t)row * 256 + col] = hp0;
                    *(uint32_t*)&g_h1lo[(size_t)row * 256 + col] = lp0;
                }
                if (row + 8 < N_NODES) {
                    *(uint32_t*)&g_h1hi[(size_t)(row + 8) * 256 + col] = hp1;
                    *(uint32_t*)&g_h1lo[(size_t)(row + 8) * 256 + col] = lp1;
                }
            } else {
                float2 v0 = make_float2(c[i][j][0], c[i][j][1]);
                float2 v1 = make_float2(c[i][j][2], c[i][j][3]);
                if (row < N_NODES)
                    *(float2*)(g_z + (size_t)row * 128 + col) = v0;
                if (row + 8 < N_NODES)
                    *(float2*)(g_z + (size_t)(row + 8) * 128 + col) = v1;
            }
        }
    }
}

// ---------------- launch ----------------------------------------------------
extern "C" void kernel_launch(void* const* d_in, const int* in_sizes, int n_in,
                              void* d_out, int out_size) {
    const float* x  = (const float*)d_in[0];
    const int*   ei = (const int*)d_in[1];
    const float* W1 = (const float*)d_in[2];
    const float* b1 = (const float*)d_in[3];
    const float* W2 = (const float*)d_in[4];
    const float* b2 = (const float*)d_in[5];
    float* out = (float*)d_out;

    cudaFuncSetAttribute(k_mma<1>, cudaFuncAttributeMaxDynamicSharedMemorySize, SM_BYTES);
    cudaFuncSetAttribute(k_mma<2>, cudaFuncAttributeMaxDynamicSharedMemorySize, SM_BYTES);

    const int T = 256;
    int gn = (N_NODES + T - 1) / T;
    int ge = (N_EDGES + T - 1) / T;

    // CSR build + weight images
    k_init<<<gn, T>>>(ei);
    k_count<<<ge, T>>>(ei);
    k_prep_w<<<256, 256>>>(W1, W2);
    k_scan<<<1, 1024>>>();
    k_scatter<<<ge, T>>>(ei);

    // layer 1: aggregate x -> bf16 images, then HMMA transform 128->256
    int gagg = (N_NODES + 7) / 8;
    int gtile = (N_NODES + 127) / 128;
    k_agg_x<<<gagg, 256>>>(x);
    {
        dim3 grid(gtile, HID_DIM / 128);
        k_mma<1><<<grid, 512, SM_BYTES>>>(b1);
    }

    // layer 2: HMMA transform 256->128, then aggregate (+b2)
    {
        dim3 grid(gtile, OUT_DIM / 128);
        k_mma<2><<<grid, 512, SM_BYTES>>>(0);
    }
    k_agg_out<<<gagg, 256>>>(b2, out);
}

// round 17
// speedup vs baseline: 1.4054x; 1.4054x over previous
#include <cuda_runtime.h>
#include <cuda_bf16.h>
#include <math.h>
#include <stdint.h>

#define N_NODES 100000
#define N_EDGES 1600000
#define IN_DIM  128
#define HID_DIM 256
#define OUT_DIM 128
#define NSCAN_B ((N_NODES + 255) / 256)     // 391 scan blocks

// ---------------- scratch (device globals; no allocation allowed) ----------
__device__ int   g_is64;
__device__ int   g_deg[N_NODES];
__device__ int   g_cur[N_NODES];
__device__ int   g_rowptr[N_NODES + 1];
__device__ int   g_bsum[NSCAN_B];
__device__ int   g_boff[NSCAN_B];
__device__ float g_dinv[N_NODES];
__device__ __align__(16) int2 g_edge[N_EDGES];         // (src, weight-as-int)
// layer-1 A (aggregated x) as bf16 hi/lo images [N,128]
__device__ __align__(16) unsigned short g_a1hi[(size_t)N_NODES * IN_DIM];
__device__ __align__(16) unsigned short g_a1lo[(size_t)N_NODES * IN_DIM];
// layer-2 A (relu(h1)) as bf16 hi/lo images [N,256]
__device__ __align__(16) unsigned short g_h1hi[(size_t)N_NODES * HID_DIM];
__device__ __align__(16) unsigned short g_h1lo[(size_t)N_NODES * HID_DIM];
__device__ __align__(16) float g_z[(size_t)N_NODES * OUT_DIM];     // h1@W2 [N,128]
// weight images W^T: [N][K] k-major bf16, hi/lo split
__device__ __align__(16) unsigned short g_w1hi[256 * 128];
__device__ __align__(16) unsigned short g_w1lo[256 * 128];
__device__ __align__(16) unsigned short g_w2hi[128 * 256];
__device__ __align__(16) unsigned short g_w2lo[128 * 256];

// ---------------- warp-level bf16 MMA (base-target PTX, runs on HMMA) ------
#define MMA_BF16(c, a, b)                                                        \
    asm volatile("mma.sync.aligned.m16n8k16.row.col.f32.bf16.bf16.f32 "          \
        "{%0,%1,%2,%3}, {%4,%5,%6,%7}, {%8,%9}, {%0,%1,%2,%3};"                  \
        : "+f"((c)[0]), "+f"((c)[1]), "+f"((c)[2]), "+f"((c)[3])                 \
        : "r"((a)[0]), "r"((a)[1]), "r"((a)[2]), "r"((a)[3]),                    \
          "r"((b)[0]), "r"((b)[1]))

#define CP_ASYNC16(dst_u32, src_ptr)                                             \
    asm volatile("cp.async.ca.shared.global [%0], [%1], 16;"                     \
                 :: "r"(dst_u32), "l"(src_ptr) : "memory")
#define CP_COMMIT() asm volatile("cp.async.commit_group;" ::: "memory")
#define CP_WAIT0()  asm volatile("cp.async.wait_group 0;" ::: "memory")

__device__ __forceinline__ uint32_t smem_u32(const void* p) {
    uint32_t a;
    asm("{ .reg .u64 t; cvta.to.shared.u64 t, %1; cvt.u32.u64 %0, t; }" : "=r"(a) : "l"(p));
    return a;
}

__device__ __forceinline__ void split2(float x, float y, uint32_t& hp, uint32_t& lp) {
    __nv_bfloat16 h0 = __float2bfloat16(x);
    __nv_bfloat16 h1 = __float2bfloat16(y);
    __nv_bfloat16 l0 = __float2bfloat16(x - __bfloat162float(h0));
    __nv_bfloat16 l1 = __float2bfloat16(y - __bfloat162float(h1));
    hp = ((uint32_t)*(unsigned short*)&h1 << 16) | *(unsigned short*)&h0;
    lp = ((uint32_t)*(unsigned short*)&l1 << 16) | *(unsigned short*)&l0;
}

// ---------------- edge_index accessors --------------------------------------
__device__ __forceinline__ int edge_src(const int* e32, int e) {
    int v = g_is64 ? e32[2 * e] : e32[e];
    return min(max(v, 0), N_NODES - 1);
}
__device__ __forceinline__ int edge_dst(const int* e32, int e) {
    int v = g_is64 ? e32[2 * (N_EDGES + e)] : e32[N_EDGES + e];
    return min(max(v, 0), N_NODES - 1);
}

// ---------------- init: zero deg/cursor + int64 dtype probe -----------------
__global__ void k_init(const int* e32) {
    int i = blockIdx.x * blockDim.x + threadIdx.x;
    if (i < N_NODES) { g_deg[i] = 0; g_cur[i] = 0; }
    if (i == 0) {
        int zeros = 0;
        for (int k = 0; k < 1024; k++) zeros += (e32[2 * k + 1] == 0) ? 1 : 0;
        g_is64 = (zeros > 512) ? 1 : 0;
    }
}

__global__ void k_count(const int* e32) {
    int e = blockIdx.x * blockDim.x + threadIdx.x;
    if (e < N_EDGES) atomicAdd(&g_deg[edge_dst(e32, e)], 1);
}

// ---------------- 3-phase parallel exclusive scan of g_deg ------------------
// phase 1: block-local scan (256 nodes/block) + dinv
__global__ void k_scan1() {
    __shared__ int sh[256];
    int t = threadIdx.x;
    int i = blockIdx.x * 256 + t;
    int d = (i < N_NODES) ? g_deg[i] : 0;
    if (i < N_NODES) g_dinv[i] = rsqrtf((float)(d + 1));   // +1 self loop
    sh[t] = d;
    __syncthreads();
#pragma unroll
    for (int off = 1; off < 256; off <<= 1) {
        int v = (t >= off) ? sh[t - off] : 0;
        __syncthreads();
        sh[t] += v;
        __syncthreads();
    }
    if (i < N_NODES) g_rowptr[i] = sh[t] - d;              // local exclusive
    if (t == 255) g_bsum[blockIdx.x] = sh[255];
}

// phase 2: scan the 391 block totals (single tiny block)
__global__ void k_scan2() {
    __shared__ int sh[512];
    int t = threadIdx.x;
    int v = (t < NSCAN_B) ? g_bsum[t] : 0;
    sh[t] = v;
    __syncthreads();
#pragma unroll
    for (int off = 1; off < 512; off <<= 1) {
        int u = (t >= off) ? sh[t - off] : 0;
        __syncthreads();
        sh[t] += u;
        __syncthreads();
    }
    if (t < NSCAN_B) g_boff[t] = sh[t] - v;                // exclusive
    if (t == NSCAN_B - 1) g_rowptr[N_NODES] = sh[t];
}

// phase 3: propagate block offsets
__global__ void k_scan3() {
    int i = blockIdx.x * 256 + threadIdx.x;
    if (i < N_NODES) g_rowptr[i] += g_boff[blockIdx.x];
}

// scatter edges (dst-sorted) with precomputed weight dinv[s]*dinv[d]
__global__ void k_scatter(const int* e32) {
    int e = blockIdx.x * blockDim.x + threadIdx.x;
    if (e < N_EDGES) {
        int s = edge_src(e32, e);
        int d = edge_dst(e32, e);
        int p = atomicAdd(&g_cur[d], 1);
        float w = g_dinv[s] * g_dinv[d];
        g_edge[g_rowptr[d] + p] = make_int2(s, __float_as_int(w));
    }
}

// ---------------- weight prep (both layers, one launch) ---------------------
__global__ void k_prep_w(const float* W1, const float* W2) {
    int idx = blockIdx.x * blockDim.x + threadIdx.x;
    if (idx < 128 * 256) {                 // W1[128k,256n] -> g_w1*[n][k]
        int n = idx & 255, k = idx >> 8;
        float x = W1[k * 256 + n];
        __nv_bfloat16 h = __float2bfloat16(x);
        __nv_bfloat16 l = __float2bfloat16(x - __bfloat162float(h));
        g_w1hi[n * 128 + k] = *(unsigned short*)&h;
        g_w1lo[n * 128 + k] = *(unsigned short*)&l;
    } else if (idx < 2 * 128 * 256) {      // W2[256k,128n] -> g_w2*[n][k]
        int r = idx - 128 * 256;
        int n = r & 127, k = r >> 7;
        float x = W2[k * 128 + n];
        __nv_bfloat16 h = __float2bfloat16(x);
        __nv_bfloat16 l = __float2bfloat16(x - __bfloat162float(h));
        g_w2hi[n * 256 + k] = *(unsigned short*)&h;
        g_w2lo[n * 256 + k] = *(unsigned short*)&l;
    }
}

// ---------------- aggregation core (8-unrolled, packed edge reads) ----------
__device__ __forceinline__ float4 agg_core(const float4* xi, int i, int lane) {
    float di = g_dinv[i];
    float4 xv = xi[(size_t)i * 32 + lane];
    float w = di * di;
    float4 acc;
    acc.x = w * xv.x; acc.y = w * xv.y; acc.z = w * xv.z; acc.w = w * xv.w;

    int j = g_rowptr[i];
    int end = g_rowptr[i + 1];
    for (; j + 7 < end; j += 8) {
        int2 e0 = g_edge[j],     e1 = g_edge[j + 1];
        int2 e2 = g_edge[j + 2], e3 = g_edge[j + 3];
        int2 e4 = g_edge[j + 4], e5 = g_edge[j + 5];
        int2 e6 = g_edge[j + 6], e7 = g_edge[j + 7];
        float4 v0 = xi[(size_t)e0.x * 32 + lane];
        float4 v1 = xi[(size_t)e1.x * 32 + lane];
        float4 v2 = xi[(size_t)e2.x * 32 + lane];
        float4 v3 = xi[(size_t)e3.x * 32 + lane];
        float4 v4 = xi[(size_t)e4.x * 32 + lane];
        float4 v5 = xi[(size_t)e5.x * 32 + lane];
        float4 v6 = xi[(size_t)e6.x * 32 + lane];
        float4 v7 = xi[(size_t)e7.x * 32 + lane];
        float w0 = __int_as_float(e0.y), w1 = __int_as_float(e1.y);
        float w2 = __int_as_float(e2.y), w3 = __int_as_float(e3.y);
        float w4 = __int_as_float(e4.y), w5 = __int_as_float(e5.y);
        float w6 = __int_as_float(e6.y), w7 = __int_as_float(e7.y);
        acc.x += ((w0 * v0.x + w1 * v1.x) + (w2 * v2.x + w3 * v3.x))
               + ((w4 * v4.x + w5 * v5.x) + (w6 * v6.x + w7 * v7.x));
        acc.y += ((w0 * v0.y + w1 * v1.y) + (w2 * v2.y + w3 * v3.y))
               + ((w4 * v4.y + w5 * v5.y) + (w6 * v6.y + w7 * v7.y));
        acc.z += ((w0 * v0.z + w1 * v1.z) + (w2 * v2.z + w3 * v3.z))
               + ((w4 * v4.z + w5 * v5.z) + (w6 * v6.z + w7 * v7.z));
        acc.w += ((w0 * v0.w + w1 * v1.w) + (w2 * v2.w + w3 * v3.w))
               + ((w4 * v4.w + w5 * v5.w) + (w6 * v6.w + w7 * v7.w));
    }
    for (; j < end; j++) {
        int2 e0 = g_edge[j];
        float w0 = __int_as_float(e0.y);
        float4 v0 = xi[(size_t)e0.x * 32 + lane];
        acc.x += w0 * v0.x; acc.y += w0 * v0.y; acc.z += w0 * v0.z; acc.w += w0 * v0.w;
    }
    return acc;
}

// pass 1: gather x fp32, write bf16 hi/lo images for GEMM1
__global__ void k_agg_x(const float* xin) {
    int warp = threadIdx.x >> 5;
    int lane = threadIdx.x & 31;
    int i = blockIdx.x * 8 + warp;
    if (i >= N_NODES) return;
    float4 acc = agg_core((const float4*)xin, i, lane);
    uint2 hp, lp;
    split2(acc.x, acc.y, hp.x, lp.x);
    split2(acc.z, acc.w, hp.y, lp.y);
    ((uint2*)g_a1hi)[(size_t)i * 32 + lane] = hp;
    ((uint2*)g_a1lo)[(size_t)i * 32 + lane] = lp;
}

// pass 2: gather g_z fp32, add bias, write final output fp32
__global__ void k_agg_out(const float* b2, float* out) {
    int warp = threadIdx.x >> 5;
    int lane = threadIdx.x & 31;
    int i = blockIdx.x * 8 + warp;
    if (i >= N_NODES) return;
    float4 acc = agg_core((const float4*)g_z, i, lane);
    acc.x += b2[lane * 4 + 0];
    acc.y += b2[lane * 4 + 1];
    acc.z += b2[lane * 4 + 2];
    acc.w += b2[lane * 4 + 3];
    ((float4*)out)[(size_t)i * 32 + lane] = acc;
}

// ---------------- bf16 split GEMM via mma.sync + cp.async tile loads --------
#define SMS 72
#define SM_BYTES (4 * 128 * SMS * 2)

template <int LAYER>
__global__ __launch_bounds__(512, 2) void k_mma(const float* bias)
{
    constexpr int KTOT = (LAYER == 1) ? 128 : 256;
    constexpr int KH   = KTOT / 64;
    const unsigned short* AHIg = (LAYER == 1) ? g_a1hi : g_h1hi;
    const unsigned short* ALOg = (LAYER == 1) ? g_a1lo : g_h1lo;
    const unsigned short* WHI  = (LAYER == 1) ? g_w1hi : g_w2hi;
    const unsigned short* WLO  = (LAYER == 1) ? g_w1lo : g_w2lo;

    extern __shared__ __align__(16) unsigned short sm[];
    unsigned short* AHI = sm;
    unsigned short* ALO = sm + 128 * SMS;
    unsigned short* BHI = sm + 2 * 128 * SMS;
    unsigned short* BLO = sm + 3 * 128 * SMS;

    int tid  = threadIdx.x;
    int lane = tid & 31;
    int wid  = tid >> 5;
    int row0 = blockIdx.x * 128;
    int nc0  = blockIdx.y * 128;

    int lr = tid >> 2;
    int cb = (tid & 3) * 16;
    int gr = min(row0 + lr, N_NODES - 1);
    uint32_t sa_hi = smem_u32(&AHI[lr * SMS + cb]);
    uint32_t sa_lo = smem_u32(&ALO[lr * SMS + cb]);
    uint32_t sb_hi = smem_u32(&BHI[lr * SMS + cb]);
    uint32_t sb_lo = smem_u32(&BLO[lr * SMS + cb]);

    float c[2][4][4];
#pragma unroll
    for (int i = 0; i < 2; i++)
#pragma unroll
        for (int j = 0; j < 4; j++)
#pragma unroll
            for (int q = 0; q < 4; q++) c[i][j][q] = 0.0f;

    for (int h = 0; h < KH; h++) {
        const unsigned short* pah = AHIg + (size_t)gr * KTOT + h * 64 + cb;
        const unsigned short* pal = ALOg + (size_t)gr * KTOT + h * 64 + cb;
        const unsigned short* pbh = WHI + (size_t)(nc0 + lr) * KTOT + h * 64 + cb;
        const unsigned short* pbl = WLO + (size_t)(nc0 + lr) * KTOT + h * 64 + cb;
        CP_ASYNC16(sa_hi,      pah);
        CP_ASYNC16(sa_hi + 16, pah + 8);
        CP_ASYNC16(sa_lo,      pal);
        CP_ASYNC16(sa_lo + 16, pal + 8);
        CP_ASYNC16(sb_hi,      pbh);
        CP_ASYNC16(sb_hi + 16, pbh + 8);
        CP_ASYNC16(sb_lo,      pbl);
        CP_ASYNC16(sb_lo + 16, pbl + 8);
        CP_COMMIT();
        CP_WAIT0();
        __syncthreads();

        int mr = (wid & 3) * 32 + (lane >> 2);
        int nr = (wid >> 2) * 32 + (lane >> 2);
#pragma unroll
        for (int k0 = 0; k0 < 64; k0 += 16) {
            int kc = k0 + (lane & 3) * 2;
            uint32_t ah[2][4], al[2][4], bh[4][2], bl[4][2];
#pragma unroll
            for (int i = 0; i < 2; i++) {
                int base = (mr + 16 * i) * SMS + kc;
                ah[i][0] = *(const uint32_t*)&AHI[base];
                ah[i][1] = *(const uint32_t*)&AHI[base + 8 * SMS];
                ah[i][2] = *(const uint32_t*)&AHI[base + 8];
                ah[i][3] = *(const uint32_t*)&AHI[base + 8 * SMS + 8];
                al[i][0] = *(const uint32_t*)&ALO[base];
                al[i][1] = *(const uint32_t*)&ALO[base + 8 * SMS];
                al[i][2] = *(const uint32_t*)&ALO[base + 8];
                al[i][3] = *(const uint32_t*)&ALO[base + 8 * SMS + 8];
            }
#pragma unroll
            for (int j = 0; j < 4; j++) {
                int base = (nr + 8 * j) * SMS + kc;
                bh[j][0] = *(const uint32_t*)&BHI[base];
                bh[j][1] = *(const uint32_t*)&BHI[base + 8];
                bl[j][0] = *(const uint32_t*)&BLO[base];
                bl[j][1] = *(const uint32_t*)&BLO[base + 8];
            }
#pragma unroll
            for (int i = 0; i < 2; i++)
#pragma unroll
                for (int j = 0; j < 4; j++) {
                    MMA_BF16(c[i][j], ah[i], bh[j]);
                    MMA_BF16(c[i][j], ah[i], bl[j]);
                    MMA_BF16(c[i][j], al[i], bh[j]);
                }
        }
        __syncthreads();
    }

    // ---- epilogue
    int m0 = (wid & 3) * 32;
    int n0 = (wid >> 2) * 32;
#pragma unroll
    for (int i = 0; i < 2; i++) {
#pragma unroll
        for (int j = 0; j < 4; j++) {
            int row = row0 + m0 + 16 * i + (lane >> 2);
            int col = nc0 + n0 + 8 * j + (lane & 3) * 2;
            if (LAYER == 1) {
                float b0 = bias[col], b1 = bias[col + 1];
                float v0x = fmaxf(c[i][j][0] + b0, 0.0f);
                float v0y = fmaxf(c[i][j][1] + b1, 0.0f);
                float v1x = fmaxf(c[i][j][2] + b0, 0.0f);
                float v1y = fmaxf(c[i][j][3] + b1, 0.0f);
                uint32_t hp0, lp0, hp1, lp1;
                split2(v0x, v0y, hp0, lp0);
                split2(v1x, v1y, hp1, lp1);
                if (row < N_NODES) {
                    *(uint32_t*)&g_h1hi[(size_t)row * 256 + col] = hp0;
                    *(uint32_t*)&g_h1lo[(size_t)row * 256 + col] = lp0;
                }
                if (row + 8 < N_NODES) {
                    *(uint32_t*)&g_h1hi[(size_t)(row + 8) * 256 + col] = hp1;
                    *(uint32_t*)&g_h1lo[(size_t)(row + 8) * 256 + col] = lp1;
                }
            } else {
                float2 v0 = make_float2(c[i][j][0], c[i][j][1]);
                float2 v1 = make_float2(c[i][j][2], c[i][j][3]);
                if (row < N_NODES)
                    *(float2*)(g_z + (size_t)row * 128 + col) = v0;
                if (row + 8 < N_NODES)
                    *(float2*)(g_z + (size_t)(row + 8) * 128 + col) = v1;
            }
        }
    }
}

// ---------------- launch ----------------------------------------------------
extern "C" void kernel_launch(void* const* d_in, const int* in_sizes, int n_in,
                              void* d_out, int out_size) {
    const float* x  = (const float*)d_in[0];
    const int*   ei = (const int*)d_in[1];
    const float* W1 = (const float*)d_in[2];
    const float* b1 = (const float*)d_in[3];
    const float* W2 = (const float*)d_in[4];
    const float* b2 = (const float*)d_in[5];
    float* out = (float*)d_out;

    cudaFuncSetAttribute(k_mma<1>, cudaFuncAttributeMaxDynamicSharedMemorySize, SM_BYTES);
    cudaFuncSetAttribute(k_mma<2>, cudaFuncAttributeMaxDynamicSharedMemorySize, SM_BYTES);

    const int T = 256;
    int gn = (N_NODES + T - 1) / T;
    int ge = (N_EDGES + T - 1) / T;

    // CSR build + weight images
    k_init<<<gn, T>>>(ei);
    k_count<<<ge, T>>>(ei);
    k_prep_w<<<256, 256>>>(W1, W2);
    k_scan1<<<NSCAN_B, 256>>>();
    k_scan2<<<1, 512>>>();
    k_scan3<<<NSCAN_B, 256>>>();
    k_scatter<<<ge, T>>>(ei);

    // layer 1: aggregate x -> bf16 images, then HMMA transform 128->256
    int gagg = (N_NODES + 7) / 8;
    int gtile = (N_NODES + 127) / 128;
    k_agg_x<<<gagg, 256>>>(x);
    {
        dim3 grid(gtile, HID_DIM / 128);
        k_mma<1><<<grid, 512, SM_BYTES>>>(b1);
    }

    // layer 2: HMMA transform 256->128, then aggregate (+b2)
    {
        dim3 grid(gtile, OUT_DIM / 128);
        k_mma<2><<<grid, 512, SM_BYTES>>>(0);
    }
    k_agg_out<<<gagg, 256>>>(b2, out);
}